// round 5
// baseline (speedup 1.0000x reference)
#include <cuda_runtime.h>
#include <cstdint>

#define Hh 16
#define Bb 4
#define Ss 1024
#define Dd 1024
#define dhd 64
#define LN_EPS 1e-5f
#define SD (Bb * Ss * Dd)          // 4M elements per [B,S,D] tensor

// Scratch (__device__ globals; allocation-free rule)
__device__ float g_inR[3 * SD];              // tf32-rounded q,k,v inputs
__device__ float g_QKV[3 * SD];              // rounded Q,K,V projections
__device__ float g_Vt[Hh * Bb * dhd * Ss];   // rounded V^T per (h,b) K-contig
__device__ float g_concat[SD];               // rounded attn@V (head-interleaved)
__device__ float g_pre[SD];
__device__ float g_WT[4 * Dd * Dd];          // rounded WqT,WkT,WvT,WoT (K-contig)

// ---------------------------------------------------------------------------
// Portable PTX helpers (sm_80-level: cp.async + mma.sync tf32)
// ---------------------------------------------------------------------------
__device__ __forceinline__ void cp16(uint32_t dst, const float* src) {
    uint64_t g = __cvta_generic_to_global((void*)src);
    asm volatile("cp.async.cg.shared.global [%0], [%1], 16;" :: "r"(dst), "l"(g));
}
__device__ __forceinline__ uint32_t smem_u32(const void* p) {
    uint32_t a;
    asm("{ .reg .u64 t; cvta.to.shared.u64 t, %1; cvt.u32.u64 %0, t; }" : "=r"(a) : "l"(p));
    return a;
}
__device__ __forceinline__ float tf32r(float x) {
    float r;
    asm("cvt.rna.tf32.f32 %0, %1;" : "=f"(r) : "f"(x));
    return r;
}
__device__ __forceinline__ void mma8(float* c, const uint32_t* a, const uint32_t* b) {
    asm volatile(
        "mma.sync.aligned.m16n8k8.row.col.f32.tf32.tf32.f32 "
        "{%0,%1,%2,%3}, {%4,%5,%6,%7}, {%8,%9}, {%0,%1,%2,%3};"
        : "+f"(c[0]), "+f"(c[1]), "+f"(c[2]), "+f"(c[3])
        : "r"(a[0]), "r"(a[1]), "r"(a[2]), "r"(a[3]), "r"(b[0]), "r"(b[1]));
}

// ---------------------------------------------------------------------------
// tf32 mma.sync GEMM: C = alpha * A @ B^T (+R). All operands pre-rounded to
// tf32 -> inner loop is pure LDS+HMMA (no cvt).
// MODE 0: plain, z-batched:  grid(N/128, M/128, NZ)
// MODE 1: causal scores tiles, grid(36, 1, 64)
// MODE 2: PV with causal K-length, grid(8, 1, 64), BN=64
// ROUND:  epilogue writes tf32-rounded values (for data feeding later GEMMs)
// ---------------------------------------------------------------------------
template <int BM, int BN, int MODE, bool ROUND>
__global__ __launch_bounds__(256)
void mma_gemm(const float* __restrict__ A, int lda, long long zsA,
              const float* __restrict__ Bm, int ldb, long long zsB,
              float* __restrict__ Cm, int ldc, long long zsC,
              const float* __restrict__ R, float alpha, int NCin)
{
    constexpr int WN_ = 32;
    constexpr int WM_ = (BN == 128) ? 64 : 32;
    constexpr int WARPS_N = BN / WN_;
    constexpr int MT = WM_ / 16, NT = WN_ / 8;
    constexpr int PAD = 20;

    __shared__ float sA[2][BM * PAD];
    __shared__ float sB[2][BN * PAD];

    const int tid = threadIdx.x, w = tid >> 5, lane = tid & 31;
    const int wm = w / WARPS_N, wn = w % WARPS_N;
    const int g = lane >> 2, tq = lane & 3;

    const float* Ap; const float* Bp; float* Cp; const float* Rp = nullptr;
    int NC;
    if constexpr (MODE == 1) {
        int idx = blockIdx.x, qt = 0;
        while (idx >= ((qt + 1) * (qt + 2)) / 2) qt++;
        const int kt = idx - (qt * (qt + 1)) / 2;
        const int z = blockIdx.z, h = z >> 2, b = z & 3;
        Ap = A + ((long long)b * Ss + qt * 128) * Dd + h * dhd;
        Bp = Bm + ((long long)b * Ss + kt * 128) * Dd + h * dhd;
        Cp = Cm + (long long)z * Ss * Ss + (long long)(qt * 128) * Ss + kt * 128;
        NC = 4;
    } else if constexpr (MODE == 2) {
        const int qt = blockIdx.x, z = blockIdx.z, h = z >> 2, b = z & 3;
        Ap = A + (long long)z * Ss * Ss + (long long)(qt * 128) * Ss;
        Bp = Bm + (long long)z * dhd * Ss;
        Cp = Cm + ((long long)b * Ss + qt * 128) * Dd + h * dhd;
        NC = (qt + 1) * 8;
    } else {
        const int z = blockIdx.z;
        Ap = A + z * zsA + (long long)blockIdx.y * 128 * lda;
        Bp = Bm + z * zsB + (long long)blockIdx.x * 128 * ldb;
        Cp = Cm + z * zsC + (long long)blockIdx.y * 128 * ldc + blockIdx.x * 128;
        if (R) Rp = R + (long long)blockIdx.y * 128 * ldc + blockIdx.x * 128;
        NC = NCin;
    }

    const uint32_t sA0 = smem_u32(&sA[0][0]), sA1 = smem_u32(&sA[1][0]);
    const uint32_t sB0 = smem_u32(&sB[0][0]), sB1 = smem_u32(&sB[1][0]);

    auto loadc = [&](int c, int p) {
        const float* a = Ap + c * 16;
        const uint32_t da = p ? sA1 : sA0;
        #pragma unroll
        for (int i = 0; i < BM * 4 / 256; i++) {
            int idx = tid + i * 256, row = idx >> 2, kq = idx & 3;
            cp16(da + (uint32_t)(row * PAD + kq * 4) * 4, a + (long long)row * lda + kq * 4);
        }
        const float* b = Bp + c * 16;
        const uint32_t db = p ? sB1 : sB0;
        #pragma unroll
        for (int i = 0; i < BN * 4 / 256; i++) {
            int idx = tid + i * 256, row = idx >> 2, kq = idx & 3;
            cp16(db + (uint32_t)(row * PAD + kq * 4) * 4, b + (long long)row * ldb + kq * 4);
        }
        asm volatile("cp.async.commit_group;" ::: "memory");
    };

    float acc[MT][NT][4];
    #pragma unroll
    for (int i = 0; i < MT; i++)
        #pragma unroll
        for (int j = 0; j < NT; j++)
            acc[i][j][0] = acc[i][j][1] = acc[i][j][2] = acc[i][j][3] = 0.f;

    loadc(0, 0);
    for (int c = 0; c < NC; c++) {
        const int p = c & 1;
        if (c + 1 < NC) {
            loadc(c + 1, p ^ 1);
            asm volatile("cp.async.wait_group 1;" ::: "memory");
        } else {
            asm volatile("cp.async.wait_group 0;" ::: "memory");
        }
        __syncthreads();

        const float* Asr = sA[p];
        const float* Bsr = sB[p];
        #pragma unroll
        for (int ks = 0; ks < 2; ks++) {
            const int k = ks * 8 + tq;
            uint32_t afr[MT][4], bfr[NT][2];
            #pragma unroll
            for (int mt = 0; mt < MT; mt++) {
                const int r = wm * WM_ + mt * 16 + g;
                afr[mt][0] = __float_as_uint(Asr[r * PAD + k]);
                afr[mt][1] = __float_as_uint(Asr[(r + 8) * PAD + k]);
                afr[mt][2] = __float_as_uint(Asr[r * PAD + k + 4]);
                afr[mt][3] = __float_as_uint(Asr[(r + 8) * PAD + k + 4]);
            }
            #pragma unroll
            for (int nt = 0; nt < NT; nt++) {
                const int n = wn * WN_ + nt * 8 + g;
                bfr[nt][0] = __float_as_uint(Bsr[n * PAD + k]);
                bfr[nt][1] = __float_as_uint(Bsr[n * PAD + k + 4]);
            }
            #pragma unroll
            for (int mt = 0; mt < MT; mt++)
                #pragma unroll
                for (int nt = 0; nt < NT; nt++)
                    mma8(acc[mt][nt], afr[mt], bfr[nt]);
        }
        __syncthreads();
    }

    #pragma unroll
    for (int mt = 0; mt < MT; mt++) {
        #pragma unroll
        for (int nt = 0; nt < NT; nt++) {
            const int r = wm * WM_ + mt * 16 + g;
            const int cc = wn * WN_ + nt * 8 + 2 * tq;
            float2 v0 = make_float2(acc[mt][nt][0] * alpha, acc[mt][nt][1] * alpha);
            float2 v1 = make_float2(acc[mt][nt][2] * alpha, acc[mt][nt][3] * alpha);
            if (MODE == 0 && Rp) {
                float2 r0 = *(const float2*)(Rp + (long long)r * ldc + cc);
                float2 r1 = *(const float2*)(Rp + (long long)(r + 8) * ldc + cc);
                v0.x += r0.x; v0.y += r0.y; v1.x += r1.x; v1.y += r1.y;
            }
            if (ROUND) {
                v0.x = tf32r(v0.x); v0.y = tf32r(v0.y);
                v1.x = tf32r(v1.x); v1.y = tf32r(v1.y);
            }
            *(float2*)(Cp + (long long)r * ldc + cc) = v0;
            *(float2*)(Cp + (long long)(r + 8) * ldc + cc) = v1;
        }
    }
}

// ---------------------------------------------------------------------------
// Round q,k,v inputs to tf32 into g_inR (concatenated).
// ---------------------------------------------------------------------------
__global__ void round_in_k(const float* __restrict__ q, const float* __restrict__ k,
                           const float* __restrict__ v, float* __restrict__ o)
{
    const long long N4 = (long long)SD / 4;                // float4s per tensor
    for (long long i = (long long)blockIdx.x * blockDim.x + threadIdx.x;
         i < 3 * N4; i += (long long)gridDim.x * blockDim.x) {
        const int t = (int)(i / N4);
        const long long j = i - (long long)t * N4;
        const float4* src = (const float4*)(t == 0 ? q : t == 1 ? k : v);
        float4 x = src[j];
        x.x = tf32r(x.x); x.y = tf32r(x.y); x.z = tf32r(x.z); x.w = tf32r(x.w);
        reinterpret_cast<float4*>(o)[i] = x;
    }
}

// ---------------------------------------------------------------------------
// Weight transposes -> [N][K] K-contig, rounded to tf32.
// ---------------------------------------------------------------------------
__global__ void transpose_w_k(const float* __restrict__ W0, const float* __restrict__ W1,
                              const float* __restrict__ W2, const float* __restrict__ W3,
                              float* __restrict__ O)
{
    __shared__ float t[32][33];
    const float* W = blockIdx.z == 0 ? W0 : blockIdx.z == 1 ? W1 : blockIdx.z == 2 ? W2 : W3;
    float* Oz = O + (long long)blockIdx.z * Dd * Dd;
    const int x0 = blockIdx.x * 32, y0 = blockIdx.y * 32;
    const int tx = threadIdx.x, ty0 = threadIdx.y;
    #pragma unroll
    for (int j = 0; j < 4; j++) {
        int ty = ty0 + j * 8;
        t[ty][tx] = tf32r(W[(long long)(y0 + ty) * Dd + x0 + tx]);
    }
    __syncthreads();
    #pragma unroll
    for (int j = 0; j < 4; j++) {
        int ty = ty0 + j * 8;
        Oz[(long long)(x0 + ty) * Dd + y0 + tx] = t[tx][ty];
    }
}

// ---------------------------------------------------------------------------
// V [B][S][D] (already rounded) -> Vt [(h*Bb+b)*64 + n][S]
// ---------------------------------------------------------------------------
__global__ void transpose_v_k(const float* __restrict__ V, float* __restrict__ Vt)
{
    __shared__ float t[32][33];
    const int s0 = blockIdx.x * 32, d0 = blockIdx.y * 32, b = blockIdx.z;
    const int tx = threadIdx.x, ty0 = threadIdx.y;
    #pragma unroll
    for (int j = 0; j < 4; j++) {
        int ty = ty0 + j * 8;
        t[ty][tx] = V[((long long)b * Ss + s0 + ty) * Dd + d0 + tx];
    }
    __syncthreads();
    const int h = d0 >> 6, n0 = d0 & 63;
    #pragma unroll
    for (int j = 0; j < 4; j++) {
        int ty = ty0 + j * 8;
        Vt[((long long)(h * Bb + b) * dhd + n0 + ty) * Ss + s0 + tx] = t[tx][ty];
    }
}

// ---------------------------------------------------------------------------
// Causal softmax in place; outputs rounded to tf32 (they feed the PV GEMM
// and are also the final attn output; tf32 rounding ~1e-4 rel).
// ---------------------------------------------------------------------------
__global__ void softmax_causal_k(float* __restrict__ A)
{
    const long long row = blockIdx.x;
    const int q = (int)(row & (Ss - 1));
    float* p = A + (row << 10);
    const int tid = threadIdx.x;
    const int j0 = tid * 4;

    float4 v = make_float4(0.f, 0.f, 0.f, 0.f);
    if (j0 <= q) v = reinterpret_cast<const float4*>(p)[tid];

    float m = -3.4e38f;
    if (j0 + 0 <= q) m = fmaxf(m, v.x);
    if (j0 + 1 <= q) m = fmaxf(m, v.y);
    if (j0 + 2 <= q) m = fmaxf(m, v.z);
    if (j0 + 3 <= q) m = fmaxf(m, v.w);

    __shared__ float red[8];
    #pragma unroll
    for (int o = 16; o; o >>= 1) m = fmaxf(m, __shfl_xor_sync(0xffffffffu, m, o));
    if ((tid & 31) == 0) red[tid >> 5] = m;
    __syncthreads();
    m = red[0];
    #pragma unroll
    for (int i = 1; i < 8; i++) m = fmaxf(m, red[i]);
    __syncthreads();

    float e0 = (j0 + 0 <= q) ? __expf(v.x - m) : 0.f;
    float e1 = (j0 + 1 <= q) ? __expf(v.y - m) : 0.f;
    float e2 = (j0 + 2 <= q) ? __expf(v.z - m) : 0.f;
    float e3 = (j0 + 3 <= q) ? __expf(v.w - m) : 0.f;

    float s = e0 + e1 + e2 + e3;
    #pragma unroll
    for (int o = 16; o; o >>= 1) s += __shfl_xor_sync(0xffffffffu, s, o);
    if ((tid & 31) == 0) red[tid >> 5] = s;
    __syncthreads();
    s = red[0];
    #pragma unroll
    for (int i = 1; i < 8; i++) s += red[i];

    const float inv = 1.0f / s;
    reinterpret_cast<float4*>(p)[tid] = make_float4(
        tf32r(e0 * inv), tf32r(e1 * inv), tf32r(e2 * inv), tf32r(e3 * inv));
}

// ---------------------------------------------------------------------------
__global__ void layernorm_k(const float* __restrict__ X,
                            const float* __restrict__ gamma,
                            const float* __restrict__ beta,
                            float* __restrict__ O)
{
    const long long row = blockIdx.x;
    const int tid = threadIdx.x;
    const float4 v = reinterpret_cast<const float4*>(X + (row << 10))[tid];

    float s  = v.x + v.y + v.z + v.w;
    float s2 = v.x * v.x + v.y * v.y + v.z * v.z + v.w * v.w;

    __shared__ float r1[8], r2[8];
    #pragma unroll
    for (int o = 16; o; o >>= 1) {
        s  += __shfl_xor_sync(0xffffffffu, s, o);
        s2 += __shfl_xor_sync(0xffffffffu, s2, o);
    }
    if ((tid & 31) == 0) { r1[tid >> 5] = s; r2[tid >> 5] = s2; }
    __syncthreads();
    s = 0.f; s2 = 0.f;
    #pragma unroll
    for (int i = 0; i < 8; i++) { s += r1[i]; s2 += r2[i]; }

    const float mean = s * (1.0f / Dd);
    const float var  = s2 * (1.0f / Dd) - mean * mean;
    const float rstd = rsqrtf(var + LN_EPS);

    const float4 g  = reinterpret_cast<const float4*>(gamma)[tid];
    const float4 be = reinterpret_cast<const float4*>(beta)[tid];
    reinterpret_cast<float4*>(O + (row << 10))[tid] = make_float4(
        (v.x - mean) * rstd * g.x + be.x,
        (v.y - mean) * rstd * g.y + be.y,
        (v.z - mean) * rstd * g.z + be.z,
        (v.w - mean) * rstd * g.w + be.w);
}

// ---------------------------------------------------------------------------
extern "C" void kernel_launch(void* const* d_in, const int* in_sizes, int n_in,
                              void* d_out, int out_size)
{
    const float* query = (const float*)d_in[0];
    const float* key   = (const float*)d_in[1];
    const float* value = (const float*)d_in[2];
    const float* Wq    = (const float*)d_in[3];
    const float* Wk    = (const float*)d_in[4];
    const float* Wv    = (const float*)d_in[5];
    const float* Wo    = (const float*)d_in[6];
    const float* gamma = (const float*)d_in[7];
    const float* beta  = (const float*)d_in[8];

    float* out  = (float*)d_out;
    float* attn = out + (long long)SD;

    float *InR, *QKV, *Vt, *Cc, *Pre, *WT;
    cudaGetSymbolAddress((void**)&InR, g_inR);
    cudaGetSymbolAddress((void**)&QKV, g_QKV);
    cudaGetSymbolAddress((void**)&Vt,  g_Vt);
    cudaGetSymbolAddress((void**)&Cc,  g_concat);
    cudaGetSymbolAddress((void**)&Pre, g_pre);
    cudaGetSymbolAddress((void**)&WT,  g_WT);

    // 0a. round inputs; 0b. transpose+round weights
    round_in_k<<<2048, 256>>>(query, key, value, InR);
    transpose_w_k<<<dim3(32, 32, 4), dim3(32, 8)>>>(Wq, Wk, Wv, Wo, WT);

    // 1. merged QKV projections (z = 0,1,2), outputs rounded
    mma_gemm<128, 128, 0, true><<<dim3(8, 32, 3), 256>>>(
        InR, Dd, (long long)SD, WT, Dd, (long long)Dd * Dd,
        QKV, Dd, (long long)SD, nullptr, 1.f, 64);

    // 2. V -> Vt (K-contig for PV; already rounded)
    transpose_v_k<<<dim3(32, 32, Bb), dim3(32, 8)>>>(QKV + 2ll * SD, Vt);

    // 3. causal scores: attn tiles = Q K^T / 8 (lower triangle only)
    mma_gemm<128, 128, 1, false><<<dim3(36, 1, Hh * Bb), 256>>>(
        QKV, Dd, 0, QKV + (long long)SD, Dd, 0, attn, Ss, 0, nullptr, 0.125f, 0);

    // 4. causal softmax in place (writes the upper-triangle zeros; rounds)
    softmax_causal_k<<<Hh * Bb * Ss, 256>>>(attn);

    // 5. PV: concat tiles (rounded), K-length = (qt+1)*128
    mma_gemm<128, 64, 2, true><<<dim3(8, 1, Hh * Bb), 256>>>(
        attn, Ss, 0, Vt, Ss, 0, Cc, Dd, 0, nullptr, 1.f, 0);

    // 6. out-proj + residual (full fp32 epilogue)
    mma_gemm<128, 128, 0, false><<<dim3(8, 32, 1), 256>>>(
        Cc, Dd, 0, WT + 3ll * Dd * Dd, Dd, 0, Pre, Dd, 0, query, 1.f, 64);

    // 7. layernorm
    layernorm_k<<<Bb * Ss, 256>>>(Pre, gamma, beta, out);
}

// round 8
// speedup vs baseline: 1.1115x; 1.1115x over previous
#include <cuda_runtime.h>
#include <cstdint>

#define Hh 16
#define Bb 4
#define Ss 1024
#define Dd 1024
#define dhd 64
#define LN_EPS 1e-5f
#define SD (Bb * Ss * Dd)

// Scratch (__device__ globals; allocation-free rule)
__device__ float g_QKV[3 * SD];              // Q,K,V projections
__device__ float g_Vt[Hh * Bb * dhd * Ss];   // V^T per (h,b) K-contig
__device__ float g_concat[SD];
__device__ float g_pre[SD];
__device__ float g_WT[4 * Dd * Dd];          // WqT,WkT,WvT,WoT (K-contig, tf32)

// ---------------------------------------------------------------------------
// Portable PTX helpers (sm_80-level)
// ---------------------------------------------------------------------------
__device__ __forceinline__ void cp16(uint32_t dst, const float* src) {
    uint64_t g = __cvta_generic_to_global((void*)src);
    asm volatile("cp.async.cg.shared.global [%0], [%1], 16;" :: "r"(dst), "l"(g));
}
__device__ __forceinline__ uint32_t smem_u32(const void* p) {
    uint32_t a;
    asm("{ .reg .u64 t; cvta.to.shared.u64 t, %1; cvt.u32.u64 %0, t; }" : "=r"(a) : "l"(p));
    return a;
}
__device__ __forceinline__ float tf32r(float x) {
    float r;
    asm("cvt.rna.tf32.f32 %0, %1;" : "=f"(r) : "f"(x));
    return r;
}
__device__ __forceinline__ uint32_t tf32u(float x) { return __float_as_uint(tf32r(x)); }

__device__ __forceinline__ void mma8(float* c, const uint32_t* a, const uint32_t* b) {
    asm volatile(
        "mma.sync.aligned.m16n8k8.row.col.f32.tf32.tf32.f32 "
        "{%0,%1,%2,%3}, {%4,%5,%6,%7}, {%8,%9}, {%0,%1,%2,%3};"
        : "+f"(c[0]), "+f"(c[1]), "+f"(c[2]), "+f"(c[3])
        : "r"(a[0]), "r"(a[1]), "r"(a[2]), "r"(a[3]), "r"(b[0]), "r"(b[1]));
}

// ---------------------------------------------------------------------------
// tf32 mma.sync GEMM: C = alpha * A @ B^T (+R).  BK=32, 2-stage cp.async.
// A: [M][K] K-contig (lda), B: [N][K] K-contig (ldb).
// MODE 0: plain, z-batched:        grid(N/128, M/128, NZ)
// MODE 1: causal scores tiles:     grid(36, 1, 64)
// MODE 2: PV with causal K-length: grid(8, 1, 64), BN=64
// ---------------------------------------------------------------------------
template <int BM, int BN, int MODE>
__global__ __launch_bounds__(256)
void mma_gemm(const float* __restrict__ A, int lda, long long zsA,
              const float* __restrict__ Bm, int ldb, long long zsB,
              float* __restrict__ Cm, int ldc, long long zsC,
              const float* __restrict__ R, float alpha, int NCin)
{
    constexpr int WN_ = 32;
    constexpr int WM_ = (BN == 128) ? 64 : 32;
    constexpr int WARPS_N = BN / WN_;
    constexpr int MT = WM_ / 16, NT = WN_ / 8;
    constexpr int PAD = 36;                    // 32 + 4 pad floats per row
    constexpr int ASTG = BM * PAD;             // floats per A stage
    constexpr int BSTG = BN * PAD;

    extern __shared__ float smem[];
    float* sA = smem;               // [2][ASTG]
    float* sB = smem + 2 * ASTG;    // [2][BSTG]
    const uint32_t sAu = smem_u32(sA);
    const uint32_t sBu = smem_u32(sB);

    const int tid = threadIdx.x, w = tid >> 5, lane = tid & 31;
    const int wm = w / WARPS_N, wn = w % WARPS_N;
    const int g = lane >> 2, tq = lane & 3;

    const float* Ap; const float* Bp; float* Cp; const float* Rp = nullptr;
    int NC;
    if constexpr (MODE == 1) {
        int idx = blockIdx.x, qt = 0;
        while (idx >= ((qt + 1) * (qt + 2)) / 2) qt++;
        const int kt = idx - (qt * (qt + 1)) / 2;
        const int z = blockIdx.z, h = z >> 2, b = z & 3;
        Ap = A + ((long long)b * Ss + qt * 128) * Dd + h * dhd;
        Bp = Bm + ((long long)b * Ss + kt * 128) * Dd + h * dhd;
        Cp = Cm + (long long)z * Ss * Ss + (long long)(qt * 128) * Ss + kt * 128;
        NC = 2;                                        // K = 64
    } else if constexpr (MODE == 2) {
        const int qt = blockIdx.x, z = blockIdx.z, h = z >> 2, b = z & 3;
        Ap = A + (long long)z * Ss * Ss + (long long)(qt * 128) * Ss;
        Bp = Bm + (long long)z * dhd * Ss;
        Cp = Cm + ((long long)b * Ss + qt * 128) * Dd + h * dhd;
        NC = (qt + 1) * 4;                             // K = (qt+1)*128
    } else {
        const int z = blockIdx.z;
        Ap = A + z * zsA + (long long)blockIdx.y * 128 * lda;
        Bp = Bm + z * zsB + (long long)blockIdx.x * 128 * ldb;
        Cp = Cm + z * zsC + (long long)blockIdx.y * 128 * ldc + blockIdx.x * 128;
        if (R) Rp = R + (long long)blockIdx.y * 128 * ldc + blockIdx.x * 128;
        NC = NCin;
    }

    auto loadc = [&](int c, int p) {
        const float* a = Ap + c * 32;
        const uint32_t da = sAu + (uint32_t)p * ASTG * 4;
        #pragma unroll
        for (int i = 0; i < BM * 8 / 256; i++) {
            int idx = tid + i * 256, row = idx >> 3, kq = idx & 7;
            cp16(da + (uint32_t)(row * PAD + kq * 4) * 4, a + (long long)row * lda + kq * 4);
        }
        const float* b = Bp + c * 32;
        const uint32_t db = sBu + (uint32_t)p * BSTG * 4;
        #pragma unroll
        for (int i = 0; i < BN * 8 / 256; i++) {
            int idx = tid + i * 256, row = idx >> 3, kq = idx & 7;
            cp16(db + (uint32_t)(row * PAD + kq * 4) * 4, b + (long long)row * ldb + kq * 4);
        }
        asm volatile("cp.async.commit_group;" ::: "memory");
    };

    float acc[MT][NT][4];
    #pragma unroll
    for (int i = 0; i < MT; i++)
        #pragma unroll
        for (int j = 0; j < NT; j++)
            acc[i][j][0] = acc[i][j][1] = acc[i][j][2] = acc[i][j][3] = 0.f;

    loadc(0, 0);
    for (int c = 0; c < NC; c++) {
        const int p = c & 1;
        if (c + 1 < NC) {
            loadc(c + 1, p ^ 1);
            asm volatile("cp.async.wait_group 1;" ::: "memory");
        } else {
            asm volatile("cp.async.wait_group 0;" ::: "memory");
        }
        __syncthreads();

        const float* Asr = sA + p * ASTG;
        const float* Bsr = sB + p * BSTG;
        #pragma unroll
        for (int ks = 0; ks < 4; ks++) {
            const int k = ks * 8 + tq;
            uint32_t afr[MT][4], bfr[NT][2];
            #pragma unroll
            for (int mt = 0; mt < MT; mt++) {
                const int r = wm * WM_ + mt * 16 + g;
                afr[mt][0] = tf32u(Asr[r * PAD + k]);
                afr[mt][1] = tf32u(Asr[(r + 8) * PAD + k]);
                afr[mt][2] = tf32u(Asr[r * PAD + k + 4]);
                afr[mt][3] = tf32u(Asr[(r + 8) * PAD + k + 4]);
            }
            #pragma unroll
            for (int nt = 0; nt < NT; nt++) {
                const int n = wn * WN_ + nt * 8 + g;
                bfr[nt][0] = tf32u(Bsr[n * PAD + k]);
                bfr[nt][1] = tf32u(Bsr[n * PAD + k + 4]);
            }
            #pragma unroll
            for (int mt = 0; mt < MT; mt++)
                #pragma unroll
                for (int nt = 0; nt < NT; nt++)
                    mma8(acc[mt][nt], afr[mt], bfr[nt]);
        }
        __syncthreads();
    }

    #pragma unroll
    for (int mt = 0; mt < MT; mt++) {
        #pragma unroll
        for (int nt = 0; nt < NT; nt++) {
            const int r = wm * WM_ + mt * 16 + g;
            const int cc = wn * WN_ + nt * 8 + 2 * tq;
            float2 v0 = make_float2(acc[mt][nt][0] * alpha, acc[mt][nt][1] * alpha);
            float2 v1 = make_float2(acc[mt][nt][2] * alpha, acc[mt][nt][3] * alpha);
            if (MODE == 0 && Rp) {
                float2 r0 = *(const float2*)(Rp + (long long)r * ldc + cc);
                float2 r1 = *(const float2*)(Rp + (long long)(r + 8) * ldc + cc);
                v0.x += r0.x; v0.y += r0.y; v1.x += r1.x; v1.y += r1.y;
            }
            *(float2*)(Cp + (long long)r * ldc + cc) = v0;
            *(float2*)(Cp + (long long)(r + 8) * ldc + cc) = v1;
        }
    }
}

// ---------------------------------------------------------------------------
// Weight transposes -> [N][K] K-contig, rounded to tf32 (free producer-side).
// ---------------------------------------------------------------------------
__global__ void transpose_w_k(const float* __restrict__ W0, const float* __restrict__ W1,
                              const float* __restrict__ W2, const float* __restrict__ W3,
                              float* __restrict__ O)
{
    __shared__ float t[32][33];
    const float* W = blockIdx.z == 0 ? W0 : blockIdx.z == 1 ? W1 : blockIdx.z == 2 ? W2 : W3;
    float* Oz = O + (long long)blockIdx.z * Dd * Dd;
    const int x0 = blockIdx.x * 32, y0 = blockIdx.y * 32;
    const int tx = threadIdx.x, ty0 = threadIdx.y;
    #pragma unroll
    for (int j = 0; j < 4; j++) {
        int ty = ty0 + j * 8;
        t[ty][tx] = tf32r(W[(long long)(y0 + ty) * Dd + x0 + tx]);
    }
    __syncthreads();
    #pragma unroll
    for (int j = 0; j < 4; j++) {
        int ty = ty0 + j * 8;
        Oz[(long long)(x0 + ty) * Dd + y0 + tx] = t[tx][ty];
    }
}

// ---------------------------------------------------------------------------
// V [B][S][D] -> Vt [(h*Bb+b)*64 + n][S]
// ---------------------------------------------------------------------------
__global__ void transpose_v_k(const float* __restrict__ V, float* __restrict__ Vt)
{
    __shared__ float t[32][33];
    const int s0 = blockIdx.x * 32, d0 = blockIdx.y * 32, b = blockIdx.z;
    const int tx = threadIdx.x, ty0 = threadIdx.y;
    #pragma unroll
    for (int j = 0; j < 4; j++) {
        int ty = ty0 + j * 8;
        t[ty][tx] = V[((long long)b * Ss + s0 + ty) * Dd + d0 + tx];
    }
    __syncthreads();
    const int h = d0 >> 6, n0 = d0 & 63;
    #pragma unroll
    for (int j = 0; j < 4; j++) {
        int ty = ty0 + j * 8;
        Vt[((long long)(h * Bb + b) * dhd + n0 + ty) * Ss + s0 + tx] = t[tx][ty];
    }
}

// ---------------------------------------------------------------------------
// Causal softmax, in place (upper triangle never read, zeros written).
// ---------------------------------------------------------------------------
__global__ void softmax_causal_k(float* __restrict__ A)
{
    const long long row = blockIdx.x;
    const int q = (int)(row & (Ss - 1));
    float* p = A + (row << 10);
    const int tid = threadIdx.x;
    const int j0 = tid * 4;

    float4 v = make_float4(0.f, 0.f, 0.f, 0.f);
    if (j0 <= q) v = reinterpret_cast<const float4*>(p)[tid];

    float m = -3.4e38f;
    if (j0 + 0 <= q) m = fmaxf(m, v.x);
    if (j0 + 1 <= q) m = fmaxf(m, v.y);
    if (j0 + 2 <= q) m = fmaxf(m, v.z);
    if (j0 + 3 <= q) m = fmaxf(m, v.w);

    __shared__ float red[8];
    #pragma unroll
    for (int o = 16; o; o >>= 1) m = fmaxf(m, __shfl_xor_sync(0xffffffffu, m, o));
    if ((tid & 31) == 0) red[tid >> 5] = m;
    __syncthreads();
    m = red[0];
    #pragma unroll
    for (int i = 1; i < 8; i++) m = fmaxf(m, red[i]);
    __syncthreads();

    float e0 = (j0 + 0 <= q) ? __expf(v.x - m) : 0.f;
    float e1 = (j0 + 1 <= q) ? __expf(v.y - m) : 0.f;
    float e2 = (j0 + 2 <= q) ? __expf(v.z - m) : 0.f;
    float e3 = (j0 + 3 <= q) ? __expf(v.w - m) : 0.f;

    float s = e0 + e1 + e2 + e3;
    #pragma unroll
    for (int o = 16; o; o >>= 1) s += __shfl_xor_sync(0xffffffffu, s, o);
    if ((tid & 31) == 0) red[tid >> 5] = s;
    __syncthreads();
    s = red[0];
    #pragma unroll
    for (int i = 1; i < 8; i++) s += red[i];

    const float inv = 1.0f / s;
    reinterpret_cast<float4*>(p)[tid] = make_float4(e0 * inv, e1 * inv, e2 * inv, e3 * inv);
}

// ---------------------------------------------------------------------------
__global__ void layernorm_k(const float* __restrict__ X,
                            const float* __restrict__ gamma,
                            const float* __restrict__ beta,
                            float* __restrict__ O)
{
    const long long row = blockIdx.x;
    const int tid = threadIdx.x;
    const float4 v = reinterpret_cast<const float4*>(X + (row << 10))[tid];

    float s  = v.x + v.y + v.z + v.w;
    float s2 = v.x * v.x + v.y * v.y + v.z * v.z + v.w * v.w;

    __shared__ float r1[8], r2[8];
    #pragma unroll
    for (int o = 16; o; o >>= 1) {
        s  += __shfl_xor_sync(0xffffffffu, s, o);
        s2 += __shfl_xor_sync(0xffffffffu, s2, o);
    }
    if ((tid & 31) == 0) { r1[tid >> 5] = s; r2[tid >> 5] = s2; }
    __syncthreads();
    s = 0.f; s2 = 0.f;
    #pragma unroll
    for (int i = 0; i < 8; i++) { s += r1[i]; s2 += r2[i]; }

    const float mean = s * (1.0f / Dd);
    const float var  = s2 * (1.0f / Dd) - mean * mean;
    const float rstd = rsqrtf(var + LN_EPS);

    const float4 g  = reinterpret_cast<const float4*>(gamma)[tid];
    const float4 be = reinterpret_cast<const float4*>(beta)[tid];
    reinterpret_cast<float4*>(O + (row << 10))[tid] = make_float4(
        (v.x - mean) * rstd * g.x + be.x,
        (v.y - mean) * rstd * g.y + be.y,
        (v.z - mean) * rstd * g.z + be.z,
        (v.w - mean) * rstd * g.w + be.w);
}

// ---------------------------------------------------------------------------
extern "C" void kernel_launch(void* const* d_in, const int* in_sizes, int n_in,
                              void* d_out, int out_size)
{
    const float* query = (const float*)d_in[0];
    const float* key   = (const float*)d_in[1];
    const float* value = (const float*)d_in[2];
    const float* Wq    = (const float*)d_in[3];
    const float* Wk    = (const float*)d_in[4];
    const float* Wv    = (const float*)d_in[5];
    const float* Wo    = (const float*)d_in[6];
    const float* gamma = (const float*)d_in[7];
    const float* beta  = (const float*)d_in[8];

    float* out  = (float*)d_out;
    float* attn = out + (long long)SD;

    float *QKV, *Vt, *Cc, *Pre, *WT;
    cudaGetSymbolAddress((void**)&QKV, g_QKV);
    cudaGetSymbolAddress((void**)&Vt,  g_Vt);
    cudaGetSymbolAddress((void**)&Cc,  g_concat);
    cudaGetSymbolAddress((void**)&Pre, g_pre);
    cudaGetSymbolAddress((void**)&WT,  g_WT);

    constexpr int PAD = 36;
    const int SM128 = (2 * 128 * PAD + 2 * 128 * PAD) * 4;  // 73728
    const int SM64  = (2 * 128 * PAD + 2 * 64 * PAD) * 4;   // 55296
    cudaFuncSetAttribute(mma_gemm<128, 128, 0>, cudaFuncAttributeMaxDynamicSharedMemorySize, SM128);
    cudaFuncSetAttribute(mma_gemm<128, 128, 1>, cudaFuncAttributeMaxDynamicSharedMemorySize, SM128);
    cudaFuncSetAttribute(mma_gemm<128, 64, 2>,  cudaFuncAttributeMaxDynamicSharedMemorySize, SM64);

    // 0. transpose + round weights
    transpose_w_k<<<dim3(32, 32, 4), dim3(32, 8)>>>(Wq, Wk, Wv, Wo, WT);

    // 1. merged QKV projections (z = 0,1,2), inputs read directly (fragment cvt)
    {
        const float* ins[3] = {query, key, value};
        // same kernel, z-batched over the three inputs via per-z A pointers:
        // A stride trick doesn't apply (separate tensors), so launch per input
        // is avoided by noting q,k,v are harness-contiguous? Not guaranteed —
        // use zsA only for B/C; do 3 launches? No: use z to index via B/C and
        // pass A per launch. Simplest safe: 3 launches kept.
        (void)ins;
    }
    mma_gemm<128, 128, 0><<<dim3(8, 32), 256, SM128>>>(
        query, Dd, 0, WT + 0ll * Dd * Dd, Dd, 0, QKV + 0ll * SD, Dd, 0, nullptr, 1.f, 32);
    mma_gemm<128, 128, 0><<<dim3(8, 32), 256, SM128>>>(
        key,   Dd, 0, WT + 1ll * Dd * Dd, Dd, 0, QKV + 1ll * SD, Dd, 0, nullptr, 1.f, 32);
    mma_gemm<128, 128, 0><<<dim3(8, 32), 256, SM128>>>(
        value, Dd, 0, WT + 2ll * Dd * Dd, Dd, 0, QKV + 2ll * SD, Dd, 0, nullptr, 1.f, 32);

    // 2. V -> Vt (K-contig for PV)
    transpose_v_k<<<dim3(32, 32, Bb), dim3(32, 8)>>>(QKV + 2ll * SD, Vt);

    // 3. causal scores: attn tiles = Q K^T / 8 (lower triangle only)
    mma_gemm<128, 128, 1><<<dim3(36, 1, Hh * Bb), 256, SM128>>>(
        QKV, Dd, 0, QKV + (long long)SD, Dd, 0, attn, Ss, 0, nullptr, 0.125f, 0);

    // 4. causal softmax in place
    softmax_causal_k<<<Hh * Bb * Ss, 256>>>(attn);

    // 5. PV: concat tiles, K-length = (qt+1)*128
    mma_gemm<128, 64, 2><<<dim3(8, 1, Hh * Bb), 256, SM64>>>(
        attn, Ss, 0, Vt, Ss, 0, Cc, Dd, 0, nullptr, 1.f, 0);

    // 6. out-proj + residual
    mma_gemm<128, 128, 0><<<dim3(8, 32), 256, SM128>>>(
        Cc, Dd, 0, WT + 3ll * Dd * Dd, Dd, 0, Pre, Dd, 0, query, 1.f, 32);

    // 7. layernorm
    layernorm_k<<<Bb * Ss, 256>>>(Pre, gamma, beta, out);
}